// round 4
// baseline (speedup 1.0000x reference)
#include <cuda_runtime.h>
#include <cuda_bf16.h>
#include <cstdint>
#include <math_constants.h>

#define NUM_CLASSES 50257
#define BLOCK_THREADS 256
#define LOG2E 1.4426950408889634f

// Fast hardware exp2 (MUFU.EX2).
__device__ __forceinline__ float ex2(float x) {
    float y;
    asm("ex2.approx.ftz.f32 %0, %1;" : "=f"(y) : "f"(x));
    return y;
}
// Fast hardware log2 (MUFU.LG2).
__device__ __forceinline__ float lg2(float x) {
    float y;
    asm("lg2.approx.ftz.f32 %0, %1;" : "=f"(y) : "f"(x));
    return y;
}

// Fused cross-block reduction state (zeroed at load; last block resets each call).
__device__ float        g_acc;
__device__ unsigned int g_count;

// Combine two log2-domain sum states (K1,s1),(K2,s2): total = s*2^K
__device__ __forceinline__ void combine2(float& K, float& s, float Ko, float so) {
    float Kn = fmaxf(K, Ko);
    s = s * ex2(K - Kn) + so * ex2(Ko - Kn);
    K = Kn;
}

__global__ __launch_bounds__(BLOCK_THREADS)
void sce_row_kernel(const float* __restrict__ inputs,
                    const int*   __restrict__ targets,
                    float*       __restrict__ out,
                    int nrows) {
    const int row = blockIdx.x;
    const int tid = threadIdx.x;
    const float* __restrict__ p = inputs + (size_t)row * NUM_CLASSES;

    // State: sum of 2^(x*log2e - Klog), split into 4 independent accumulators.
    float Klog = 0.0f;
    float s0 = 0.f, s1 = 0.f, s2 = 0.f, s3 = 0.f;

    // --- scalar head until 16B alignment (rows are only 4B-aligned) ---
    int head = (int)((4u - ((((uintptr_t)p) >> 2) & 3u)) & 3u);
    if (head > NUM_CLASSES) head = NUM_CLASSES;
    for (int i = tid; i < head; i += BLOCK_THREADS) {
        float t = __ldcs(p + i) * LOG2E;
        if (t > Klog + 80.f) {           // cold path
            float r = ex2(Klog - t);
            s0 *= r; s1 *= r; s2 *= r; s3 *= r; Klog = t;
        }
        s0 += ex2(t - Klog);
    }

    // --- vectorized streaming body: 4 front-batched float4 loads / iter ---
    const float4* __restrict__ pv = (const float4*)(p + head);
    const int nvec = (NUM_CLASSES - head) >> 2;

    int i = tid;
    for (; i + 3 * BLOCK_THREADS < nvec; i += 4 * BLOCK_THREADS) {
        float4 a = __ldcs(pv + i);
        float4 b = __ldcs(pv + i +     BLOCK_THREADS);
        float4 c = __ldcs(pv + i + 2 * BLOCK_THREADS);
        float4 d = __ldcs(pv + i + 3 * BLOCK_THREADS);

        // batch max (overflow guard only — cold for sane inputs)
        float mab = fmaxf(fmaxf(a.x, a.y), fmaxf(a.z, a.w));
        float mcd = fmaxf(fmaxf(b.x, b.y), fmaxf(b.z, b.w));
        float mef = fmaxf(fmaxf(c.x, c.y), fmaxf(c.z, c.w));
        float mgh = fmaxf(fmaxf(d.x, d.y), fmaxf(d.z, d.w));
        float mb  = fmaxf(fmaxf(mab, mcd), fmaxf(mef, mgh)) * LOG2E;
        if (mb > Klog + 80.f) {
            float r = ex2(Klog - mb);
            s0 *= r; s1 *= r; s2 *= r; s3 *= r; Klog = mb;
        }

        s0 += ex2(fmaf(a.x, LOG2E, -Klog)) + ex2(fmaf(a.y, LOG2E, -Klog));
        s1 += ex2(fmaf(a.z, LOG2E, -Klog)) + ex2(fmaf(a.w, LOG2E, -Klog));
        s2 += ex2(fmaf(b.x, LOG2E, -Klog)) + ex2(fmaf(b.y, LOG2E, -Klog));
        s3 += ex2(fmaf(b.z, LOG2E, -Klog)) + ex2(fmaf(b.w, LOG2E, -Klog));
        s0 += ex2(fmaf(c.x, LOG2E, -Klog)) + ex2(fmaf(c.y, LOG2E, -Klog));
        s1 += ex2(fmaf(c.z, LOG2E, -Klog)) + ex2(fmaf(c.w, LOG2E, -Klog));
        s2 += ex2(fmaf(d.x, LOG2E, -Klog)) + ex2(fmaf(d.y, LOG2E, -Klog));
        s3 += ex2(fmaf(d.z, LOG2E, -Klog)) + ex2(fmaf(d.w, LOG2E, -Klog));
    }
    // leftover float4s
    for (; i < nvec; i += BLOCK_THREADS) {
        float4 a = __ldcs(pv + i);
        float mb = fmaxf(fmaxf(a.x, a.y), fmaxf(a.z, a.w)) * LOG2E;
        if (mb > Klog + 80.f) {
            float r = ex2(Klog - mb);
            s0 *= r; s1 *= r; s2 *= r; s3 *= r; Klog = mb;
        }
        s0 += ex2(fmaf(a.x, LOG2E, -Klog)) + ex2(fmaf(a.y, LOG2E, -Klog));
        s1 += ex2(fmaf(a.z, LOG2E, -Klog)) + ex2(fmaf(a.w, LOG2E, -Klog));
    }
    // scalar tail
    const int tail_start = head + (nvec << 2);
    for (int j = tail_start + tid; j < NUM_CLASSES; j += BLOCK_THREADS) {
        float t = __ldcs(p + j) * LOG2E;
        if (t > Klog + 80.f) {
            float r = ex2(Klog - t);
            s0 *= r; s1 *= r; s2 *= r; s3 *= r; Klog = t;
        }
        s0 += ex2(t - Klog);
    }

    float s = (s0 + s1) + (s2 + s3);

    // --- warp reduction of (Klog, s) ---
    #pragma unroll
    for (int off = 16; off > 0; off >>= 1) {
        float Ko = __shfl_down_sync(0xFFFFFFFFu, Klog, off);
        float so = __shfl_down_sync(0xFFFFFFFFu, s,    off);
        combine2(Klog, s, Ko, so);
    }

    // --- cross-warp reduction in shared ---
    __shared__ float sh_K[BLOCK_THREADS / 32];
    __shared__ float sh_s[BLOCK_THREADS / 32];
    const int wid = tid >> 5;
    const int lid = tid & 31;
    if (lid == 0) { sh_K[wid] = Klog; sh_s[wid] = s; }
    __syncthreads();

    if (wid == 0) {
        const int nwarps = BLOCK_THREADS / 32;   // 8
        Klog = (lid < nwarps) ? sh_K[lid] : -CUDART_INF_F;
        s    = (lid < nwarps) ? sh_s[lid] : 0.0f;
        #pragma unroll
        for (int off = 4; off > 0; off >>= 1) {
            float Ko = __shfl_down_sync(0xFFFFFFFFu, Klog, off);
            float so = __shfl_down_sync(0xFFFFFFFFu, s,    off);
            combine2(Klog, s, Ko, so);
        }
        if (lid == 0) {
            int   t  = __ldg(targets + row);
            float xt = __ldg(p + t);                      // L2 hit (row just streamed)
            // log p_t = x_t - lse,  lse = (Klog + log2 s)/log2e
            float logp = xt - (Klog + lg2(s)) * (1.0f / LOG2E);

            atomicAdd(&g_acc, logp);
            __threadfence();
            unsigned int ticket = atomicInc(&g_count, (unsigned int)(gridDim.x - 1));
            if (ticket == (unsigned int)(gridDim.x - 1)) {
                float total = atomicAdd(&g_acc, 0.0f);    // coherent read
                double scale = 1.0 - 0.154 + 0.154 / (double)NUM_CLASSES;
                double mean_logp = (double)total / (double)nrows;
                out[0] = (float)(-(mean_logp + log(scale)));
                g_acc = 0.0f;                              // reset for next replay
            }
        }
    }
}

extern "C" void kernel_launch(void* const* d_in, const int* in_sizes, int n_in,
                              void* d_out, int out_size) {
    const float* inputs  = (const float*)d_in[0];
    const int*   targets = (const int*)d_in[1];
    float*       out     = (float*)d_out;

    const int nrows = in_sizes[1];
    sce_row_kernel<<<nrows, BLOCK_THREADS>>>(inputs, targets, out, nrows);
}

// round 5
// speedup vs baseline: 1.0417x; 1.0417x over previous
#include <cuda_runtime.h>
#include <cuda_bf16.h>
#include <cstdint>
#include <math_constants.h>

#define NUM_CLASSES 50257
#define BLOCK_THREADS 512

// Fused cross-block reduction state (zeroed at load; last block resets each call).
__device__ float        g_acc;
__device__ unsigned int g_count;

// Combine two online-softmax states (m1,s1) and (m2,s2).
__device__ __forceinline__ void combine(float& m, float& s, float mo, float so) {
    float mn = fmaxf(m, mo);
    s = s * __expf(m - mn) + so * __expf(mo - mn);
    m = mn;
}

__global__ __launch_bounds__(BLOCK_THREADS)
void sce_row_kernel(const float* __restrict__ inputs,
                    const int*   __restrict__ targets,
                    float*       __restrict__ out,
                    int nrows) {
    const int row = blockIdx.x;
    const int tid = threadIdx.x;
    const float* __restrict__ p = inputs + (size_t)row * NUM_CLASSES;

    float m = -CUDART_INF_F;
    float s = 0.0f;

    // --- scalar head until 16B alignment (rows are only 4B-aligned) ---
    int head = (int)((4u - ((((uintptr_t)p) >> 2) & 3u)) & 3u);
    if (head > NUM_CLASSES) head = NUM_CLASSES;
    for (int i = tid; i < head; i += BLOCK_THREADS) {
        float x = __ldcs(p + i);
        float mn = fmaxf(m, x);
        s = s * __expf(m - mn) + __expf(x - mn);
        m = mn;
    }

    // --- vectorized streaming body (evict-first) ---
    const float4* __restrict__ pv = (const float4*)(p + head);
    const int nvec = (NUM_CLASSES - head) >> 2;
    #pragma unroll 4
    for (int i = tid; i < nvec; i += BLOCK_THREADS) {
        float4 v = __ldcs(pv + i);
        float m4 = fmaxf(fmaxf(v.x, v.y), fmaxf(v.z, v.w));
        float mn = fmaxf(m, m4);
        s = s * __expf(m - mn)
          + __expf(v.x - mn) + __expf(v.y - mn)
          + __expf(v.z - mn) + __expf(v.w - mn);
        m = mn;
    }

    // --- scalar tail ---
    const int tail_start = head + (nvec << 2);
    for (int i = tail_start + tid; i < NUM_CLASSES; i += BLOCK_THREADS) {
        float x = __ldcs(p + i);
        float mn = fmaxf(m, x);
        s = s * __expf(m - mn) + __expf(x - mn);
        m = mn;
    }

    // --- warp reduction of (m, s) ---
    #pragma unroll
    for (int off = 16; off > 0; off >>= 1) {
        float mo = __shfl_down_sync(0xFFFFFFFFu, m, off);
        float so = __shfl_down_sync(0xFFFFFFFFu, s, off);
        combine(m, s, mo, so);
    }

    // --- cross-warp reduction in shared ---
    __shared__ float sh_m[BLOCK_THREADS / 32];
    __shared__ float sh_s[BLOCK_THREADS / 32];
    const int wid = tid >> 5;
    const int lid = tid & 31;
    if (lid == 0) { sh_m[wid] = m; sh_s[wid] = s; }
    __syncthreads();

    if (wid == 0) {
        const int nwarps = BLOCK_THREADS / 32;   // 16
        m = (lid < nwarps) ? sh_m[lid] : -CUDART_INF_F;
        s = (lid < nwarps) ? sh_s[lid] : 0.0f;
        #pragma unroll
        for (int off = 8; off > 0; off >>= 1) {
            float mo = __shfl_down_sync(0xFFFFFFFFu, m, off);
            float so = __shfl_down_sync(0xFFFFFFFFu, s, off);
            combine(m, s, mo, so);
        }
        if (lid == 0) {
            int   t  = __ldg(targets + row);
            float xt = __ldg(p + t);                 // L2 hit (row just streamed)
            float logp = xt - m - __logf(s);         // log p_t

            // fused cross-block reduction
            atomicAdd(&g_acc, logp);
            __threadfence();
            unsigned int ticket = atomicInc(&g_count, (unsigned int)(gridDim.x - 1));
            if (ticket == (unsigned int)(gridDim.x - 1)) {
                float total = atomicAdd(&g_acc, 0.0f);   // coherent read
                double scale = 1.0 - 0.154 + 0.154 / (double)NUM_CLASSES;
                double mean_logp = (double)total / (double)nrows;
                out[0] = (float)(-(mean_logp + log(scale)));
                g_acc = 0.0f;                             // reset for next replay
            }
        }
    }
}

extern "C" void kernel_launch(void* const* d_in, const int* in_sizes, int n_in,
                              void* d_out, int out_size) {
    const float* inputs  = (const float*)d_in[0];
    const int*   targets = (const int*)d_in[1];
    float*       out     = (float*)d_out;

    const int nrows = in_sizes[1];
    sce_row_kernel<<<nrows, BLOCK_THREADS>>>(inputs, targets, out, nrows);
}